// round 16
// baseline (speedup 1.0000x reference)
#include <cuda_runtime.h>
#include <cstdint>

#define B_ 4
#define H_ 16
#define S_ 1024
#define D_ 64
#define NTOT   ((size_t)B_ * H_ * S_ * S_)
#define NWORDS (NTOT / 32)

#define KEEP_THRESH 0xE6666600u   // bits < thresh  <=>  uniform < 0.9f (verified)

__device__ uint32_t g_mask[NWORDS];             // 8 MB dropout bitmask
__device__ uint32_t g_k[B_ * H_ * S_ * D_];     // 16 MB: K bf16 hi/lo packed
__device__ uint32_t g_v[B_ * H_ * S_ * D_];     // 16 MB: V^T bf16 hi/lo packed

// g_k row (bh*1024 + key): [hi word(d-pair 0..31) | lo word 0..31]   (64 words)
// g_v row (bh*1024 + t*64 + d): [hi word(kp 0..31) | lo word 0..31]  (64 words)

// ---------------------------------------------------------------------------
// Threefry-2x32, key (0,42), JAX partitionable path (bit-exact, verified)
// ---------------------------------------------------------------------------
__device__ __forceinline__ void threefry2x32(uint32_t k0, uint32_t k1,
                                             uint32_t& x0, uint32_t& x1) {
    uint32_t ks2 = 0x1BD11BDAu ^ k0 ^ k1;
    x0 += k0; x1 += k1;
#define TF_RND(r) { x0 += x1; x1 = __funnelshift_l(x1, x1, (r)); x1 ^= x0; }
    TF_RND(13) TF_RND(15) TF_RND(26) TF_RND(6)
    x0 += k1;  x1 += ks2 + 1u;
    TF_RND(17) TF_RND(29) TF_RND(16) TF_RND(24)
    x0 += ks2; x1 += k0 + 2u;
    TF_RND(13) TF_RND(15) TF_RND(26) TF_RND(6)
    x0 += k0;  x1 += k1 + 3u;
    TF_RND(17) TF_RND(29) TF_RND(16) TF_RND(24)
    x0 += k1;  x1 += ks2 + 4u;
    TF_RND(13) TF_RND(15) TF_RND(26) TF_RND(6)
    x0 += ks2; x1 += k0 + 5u;
#undef TF_RND
}

// ---------------------------------------------------------------------------
// bf16 helpers
// ---------------------------------------------------------------------------
__device__ __forceinline__ uint32_t pack2(float lo, float hi) {
    uint32_t r;
    asm("cvt.rn.bf16x2.f32 %0, %1, %2;" : "=r"(r) : "f"(hi), "f"(lo));
    return r;
}
__device__ __forceinline__ float blo(uint32_t w) { return __uint_as_float(w << 16); }
__device__ __forceinline__ float bhi(uint32_t w) { return __uint_as_float(w & 0xffff0000u); }
__device__ __forceinline__ void split2(float a, float b, uint32_t& h, uint32_t& l) {
    h = pack2(a, b);
    l = pack2(a - blo(h), b - bhi(h));
}

// ---------------------------------------------------------------------------
// Kernel 1: dropout mask (blocks 0..8191) + K convert (8192..9215)
//           + V convert/transpose (9216..10239)   [identical to R13]
// ---------------------------------------------------------------------------
#define MASK_BLKS 8192
#define KC_BLKS   1024
#define VSTR      65

__global__ void __launch_bounds__(256) prep_kernel(const float* __restrict__ K,
                                                   const float* __restrict__ V) {
    __shared__ float vsm[64 * VSTR];
    const int b = blockIdx.x;
    const int tid = threadIdx.x;

    if (b < MASK_BLKS) {
        uint32_t base = (uint32_t)(b * 256 + tid) * 32u;
        uint32_t w = 0u;
#pragma unroll 4
        for (int i = 0; i < 32; i++) {
            uint32_t x0 = 0u, x1 = base + (uint32_t)i;
            threefry2x32(0u, 42u, x0, x1);
            w |= (((x0 ^ x1) < KEEP_THRESH) ? 1u : 0u) << i;
        }
        g_mask[b * 256 + tid] = w;
    } else if (b < MASK_BLKS + KC_BLKS) {
        int grow = (b - MASK_BLKS) * 64 + (tid >> 2);
        int q = tid & 3;
        const float4* src = reinterpret_cast<const float4*>(K + grow * 64 + q * 16);
        uint32_t hw[8], lw[8];
#pragma unroll
        for (int i = 0; i < 4; i++) {
            float4 v = src[i];
            split2(v.x, v.y, hw[2 * i],     lw[2 * i]);
            split2(v.z, v.w, hw[2 * i + 1], lw[2 * i + 1]);
        }
        uint32_t* dst = g_k + grow * 64;
        *reinterpret_cast<uint4*>(dst + 8 * q)      = make_uint4(hw[0], hw[1], hw[2], hw[3]);
        *reinterpret_cast<uint4*>(dst + 8 * q + 4)  = make_uint4(hw[4], hw[5], hw[6], hw[7]);
        *reinterpret_cast<uint4*>(dst + 32 + 8 * q)     = make_uint4(lw[0], lw[1], lw[2], lw[3]);
        *reinterpret_cast<uint4*>(dst + 32 + 8 * q + 4) = make_uint4(lw[4], lw[5], lw[6], lw[7]);
    } else {
        int bb = b - MASK_BLKS - KC_BLKS;
        const float* Vt = V + (size_t)bb * 64 * 64;
#pragma unroll
        for (int i = 0; i < 4; i++) {
            int lin = tid + (i << 8);
            int row = lin >> 4, qd = (lin & 15) << 2;
            float4 v = *reinterpret_cast<const float4*>(Vt + row * 64 + qd);
            float* d = vsm + row * VSTR + qd;
            d[0] = v.x; d[1] = v.y; d[2] = v.z; d[3] = v.w;
        }
        __syncthreads();
        int od = tid >> 2;
        int kq = tid & 3;
        uint32_t hw[8], lw[8];
#pragma unroll
        for (int j = 0; j < 8; j++) {
            int kp = kq * 8 + j;
            float f0 = vsm[(2 * kp) * VSTR + od];
            float f1 = vsm[(2 * kp + 1) * VSTR + od];
            split2(f0, f1, hw[j], lw[j]);
        }
        uint32_t* dst = g_v + ((size_t)bb * 64 + od) * 64;
        *reinterpret_cast<uint4*>(dst + 8 * kq)      = make_uint4(hw[0], hw[1], hw[2], hw[3]);
        *reinterpret_cast<uint4*>(dst + 8 * kq + 4)  = make_uint4(hw[4], hw[5], hw[6], hw[7]);
        *reinterpret_cast<uint4*>(dst + 32 + 8 * kq)     = make_uint4(lw[0], lw[1], lw[2], lw[3]);
        *reinterpret_cast<uint4*>(dst + 32 + 8 * kq + 4) = make_uint4(lw[4], lw[5], lw[6], lw[7]);
    }
}

// ---------------------------------------------------------------------------
// Attention: single KV buffer, 3 CTAs/SM (occupancy attacks the phase convoy)
// ---------------------------------------------------------------------------
__device__ __forceinline__ void mma16(float d[4], const uint32_t a[4],
                                      uint32_t b0, uint32_t b1) {
    asm volatile(
        "mma.sync.aligned.m16n8k16.row.col.f32.bf16.bf16.f32 "
        "{%0,%1,%2,%3}, {%4,%5,%6,%7}, {%8,%9}, {%0,%1,%2,%3};"
        : "+f"(d[0]), "+f"(d[1]), "+f"(d[2]), "+f"(d[3])
        : "r"(a[0]), "r"(a[1]), "r"(a[2]), "r"(a[3]), "r"(b0), "r"(b1));
}
__device__ __forceinline__ void ldm_x4(uint32_t r[4], uint32_t addr) {
    asm volatile("ldmatrix.sync.aligned.m8n8.x4.shared.b16 {%0,%1,%2,%3}, [%4];"
                 : "=r"(r[0]), "=r"(r[1]), "=r"(r[2]), "=r"(r[3]) : "r"(addr));
}
__device__ __forceinline__ void cp16(uint32_t saddr, const void* g) {
    asm volatile("cp.async.cg.shared.global [%0], [%1], 16;"
                 :: "r"(saddr), "l"(g));
}

#define PW 36   // bf16x2 word stride: 144 B/row, conflict-free ldmatrix

// smem word offsets: Q + ONE K/V buffer
#define W_QH  0
#define W_QL  (128 * PW)                 // 4608
#define W_KH0 (2 * 128 * PW)             // 9216
#define W_KL0 (W_KH0 + 64 * PW)
#define W_VH0 (W_KH0 + 2 * 64 * PW)
#define W_VL0 (W_KH0 + 3 * 64 * PW)
#define W_TOT (W_KH0 + 4 * 64 * PW)      // 18432 words = 73728 B -> 3 CTAs/SM

__global__ void __launch_bounds__(256, 3)
attn_kernel(const float* __restrict__ Q, const uint32_t* __restrict__ scale_ptr,
            float* __restrict__ O) {
    extern __shared__ uint32_t smw[];

    const int tid  = threadIdx.x;
    const int warp = tid >> 5;
    const int lane = tid & 31;
    const int gid  = lane >> 2;
    const int tig  = lane & 3;
    const int bh   = blockIdx.y;
    const int qb   = blockIdx.x << 7;
    const int r0   = warp * 16 + gid;

    uint32_t sw = *scale_ptr;
    float scale = (sw & 0x7f800000u) ? __uint_as_float(sw) : (float)(int)sw;

    const uint32_t sb = (uint32_t)__cvta_generic_to_shared(smw);
    const uint32_t laneA = (uint32_t)((lane & 15) * PW + ((lane & 16) ? 4 : 0));
    const uint32_t laneBK = (uint32_t)(((lane < 16) ? W_KH0 : W_KL0)
                                       + (lane & 7) * PW + ((lane & 8) ? 4 : 0));
    const uint32_t laneBV = (uint32_t)(((lane < 16) ? W_VH0 : W_VL0)
                                       + (lane & 7) * PW + ((lane & 8) ? 4 : 0));
    const uint32_t aQH = sb + 4u * (W_QH + (uint32_t)(warp * 16) * PW + laneA);
    const uint32_t aQL = sb + 4u * (W_QL + (uint32_t)(warp * 16) * PW + laneA);
    const uint32_t aK  = sb + 4u * laneBK;
    const uint32_t aV  = sb + 4u * laneBV;

    // cp.async chunk map: 2048 chunks (K:1024, V:1024), 8 per thread
    const uint32_t kv_rowbase = (uint32_t)(bh * 1024) * 64u;

    // ---- prologue: prefetch tile 0 into the buffer ----
#pragma unroll
    for (int i = 0; i < 8; i++) {
        int lin = tid + (i << 8);
        int tensor = lin >> 10;
        int r = (lin >> 4) & 63, c = lin & 15;
        uint32_t soff = kv_rowbase + (uint32_t)(r * 64 + ((c & 8) ? 32 : 0) + 4 * (c & 7));
        const uint32_t* src = (tensor ? g_v : g_k) + soff;
        uint32_t dw = (tensor ? (c < 8 ? W_VH0 : W_VL0) : (c < 8 ? W_KH0 : W_KL0))
                      + (uint32_t)(r * PW + 4 * (c & 7));
        cp16(sb + 4u * dw, src);
    }
    asm volatile("cp.async.commit_group;" ::: "memory");

    // ---- Q prologue: stage scaled hi/lo bf16x2 words into smem ----
    {
        int r = tid >> 1, half = (tid & 1) * 32;
        const float4* Qp = reinterpret_cast<const float4*>(
            Q + ((size_t)bh * S_ + qb + r) * D_ + half);
        int wb = r * PW + (half >> 1);
#pragma unroll
        for (int i = 0; i < 8; i++) {
            float4 v = Qp[i];
            uint32_t h0, l0, h1, l1;
            split2(v.x * scale, v.y * scale, h0, l0);
            split2(v.z * scale, v.w * scale, h1, l1);
            smw[W_QH + wb + 2 * i]     = h0;
            smw[W_QH + wb + 2 * i + 1] = h1;
            smw[W_QL + wb + 2 * i]     = l0;
            smw[W_QL + wb + 2 * i + 1] = l1;
        }
    }

    float m_[2], l_[2];
    float o[8][4];
    m_[0] = m_[1] = -1e30f;
    l_[0] = l_[1] = 0.f;
#pragma unroll
    for (int n = 0; n < 8; n++)
#pragma unroll
        for (int c = 0; c < 4; c++) o[n][c] = 0.f;

#pragma unroll 1
    for (int t = 0; t < 16; t++) {
        // ---- mask prefetch (hidden under QK) ----
        uint2 mw[2];
#pragma unroll
        for (int h = 0; h < 2; h++) {
            size_t rg = (size_t)(bh * S_ + qb + r0 + 8 * h);
            mw[h] = *reinterpret_cast<const uint2*>(g_mask + (rg << 5) + t * 2);
        }

        asm volatile("cp.async.wait_group 0;" ::: "memory");
        __syncthreads();                 // tile t resident

        // ---- QK: 3-term bf16 ----
        float s[8][4];
#pragma unroll
        for (int n = 0; n < 8; n++)
#pragma unroll
            for (int c = 0; c < 4; c++) s[n][c] = 0.f;

#pragma unroll
        for (int ks = 0; ks < 4; ks++) {
            uint32_t qh[4], ql[4];
            ldm_x4(qh, aQH + ks * 32u);
            ldm_x4(ql, aQL + ks * 32u);
#pragma unroll
            for (int n = 0; n < 8; n++) {
                uint32_t kb[4];
                ldm_x4(kb, aK + 4u * (uint32_t)(n * 8 * PW + ks * 8));
                mma16(s[n], qh, kb[0], kb[1]);
                mma16(s[n], ql, kb[0], kb[1]);
                mma16(s[n], qh, kb[2], kb[3]);
            }
        }

        // ---- online softmax ----
#pragma unroll
        for (int h = 0; h < 2; h++) {
            float mx = -1e30f;
#pragma unroll
            for (int n = 0; n < 8; n++)
                mx = fmaxf(mx, fmaxf(s[n][2 * h], s[n][2 * h + 1]));
            mx = fmaxf(mx, __shfl_xor_sync(0xffffffffu, mx, 1));
            mx = fmaxf(mx, __shfl_xor_sync(0xffffffffu, mx, 2));
            float mnew = fmaxf(m_[h], mx);
            float corr = __expf(m_[h] - mnew);
            m_[h] = mnew;
            float sum = 0.f;
#pragma unroll
            for (int n = 0; n < 8; n++) {
                float e0 = __expf(s[n][2 * h] - mnew);
                float e1 = __expf(s[n][2 * h + 1] - mnew);
                s[n][2 * h] = e0;
                s[n][2 * h + 1] = e1;
                sum += e0 + e1;
            }
            sum += __shfl_xor_sync(0xffffffffu, sum, 1);
            sum += __shfl_xor_sync(0xffffffffu, sum, 2);
            l_[h] = l_[h] * corr + sum;
#pragma unroll
            for (int n = 0; n < 8; n++) {
                o[n][2 * h] *= corr;
                o[n][2 * h + 1] *= corr;
            }
        }

        // ---- PV: dropout + pack P in regs ----
#pragma unroll
        for (int ks = 0; ks < 4; ks++) {
            uint32_t aph[4], apl[4];
#pragma unroll
            for (int q = 0; q < 4; q++) {
                int n = 2 * ks + (q >> 1);
                int h = q & 1;
                uint32_t word = (n < 4) ? mw[h].x : mw[h].y;
                int bit0 = (n & 3) * 8 + 2 * tig;
                float p0 = ((word >> bit0) & 1u) ? s[n][2 * h] : 0.f;
                float p1 = ((word >> (bit0 + 1)) & 1u) ? s[n][2 * h + 1] : 0.f;
                int ar = (q >> 1) * 2 + h;
                split2(p0, p1, aph[ar], apl[ar]);
            }
#pragma unroll
            for (int n = 0; n < 8; n++) {
                uint32_t vb[4];
                ldm_x4(vb, aV + 4u * (uint32_t)(n * 8 * PW + ks * 8));
                mma16(o[n], aph, vb[0], vb[1]);
                mma16(o[n], aph, vb[2], vb[3]);
                mma16(o[n], apl, vb[0], vb[1]);
            }
        }

        __syncthreads();                 // all warps done with the buffer

        // ---- prefetch tile t+1 ----
        if (t < 15) {
            uint32_t srcb = kv_rowbase + (uint32_t)((t + 1) * 64) * 64u;
#pragma unroll
            for (int i = 0; i < 8; i++) {
                int lin = tid + (i << 8);
                int tensor = lin >> 10;
                int r = (lin >> 4) & 63, c = lin & 15;
                uint32_t soff = srcb + (uint32_t)(r * 64 + ((c & 8) ? 32 : 0) + 4 * (c & 7));
                const uint32_t* src = (tensor ? g_v : g_k) + soff;
                uint32_t dw = (tensor ? (c < 8 ? W_VH0 : W_VL0) : (c < 8 ? W_KH0 : W_KL0))
                              + (uint32_t)(r * PW + 4 * (c & 7));
                cp16(sb + 4u * dw, src);
            }
        }
        asm volatile("cp.async.commit_group;" ::: "memory");
    }

    // ---- epilogue: O / (0.9 * l) ----
#pragma unroll
    for (int h = 0; h < 2; h++) {
        float inv = 1.f / (0.9f * l_[h]);
        int row = qb + r0 + h * 8;
        float* Op = O + ((size_t)bh * S_ + row) * D_;
#pragma unroll
        for (int n = 0; n < 8; n++) {
            float2 v;
            v.x = o[n][2 * h] * inv;
            v.y = o[n][2 * h + 1] * inv;
            *reinterpret_cast<float2*>(Op + n * 8 + 2 * tig) = v;
        }
    }
}

// ---------------------------------------------------------------------------
extern "C" void kernel_launch(void* const* d_in, const int* in_sizes, int n_in,
                              void* d_out, int out_size) {
    (void)in_sizes; (void)n_in; (void)out_size;
    const float*    Q  = (const float*)d_in[0];
    const float*    K  = (const float*)d_in[1];
    const float*    V  = (const float*)d_in[2];
    const uint32_t* SC = (const uint32_t*)d_in[3];
    float*          O  = (float*)d_out;

    prep_kernel<<<MASK_BLKS + 2 * KC_BLKS, 256>>>(K, V);

    const int smem = W_TOT * (int)sizeof(uint32_t);   // 73728 B
    cudaFuncSetAttribute(attn_kernel,
                         cudaFuncAttributeMaxDynamicSharedMemorySize, smem);
    dim3 grid(S_ / 128, B_ * H_);
    attn_kernel<<<grid, 256, smem>>>(Q, SC, O);
}

// round 17
// speedup vs baseline: 1.1694x; 1.1694x over previous
#include <cuda_runtime.h>
#include <cstdint>

#define B_ 4
#define H_ 16
#define S_ 1024
#define D_ 64
#define NTOT   ((size_t)B_ * H_ * S_ * S_)
#define NWORDS (NTOT / 32)

#define KEEP_THRESH 0xE6666600u   // bits < thresh  <=>  uniform < 0.9f (verified)

__device__ uint32_t g_mask[NWORDS];             // 8 MB dropout bitmask
__device__ uint32_t g_k[B_ * H_ * S_ * D_];     // 16 MB: K bf16 hi/lo packed
__device__ uint32_t g_v[B_ * H_ * S_ * D_ / 2]; // 8 MB: V^T fp16 single packed

// g_k row (bh*1024 + key): [hi word(d-pair 0..31) | lo word 0..31] (64 words)
// g_v row (bh*1024 + t*64 + d): word kp = fp16 pair (key 2kp, 2kp+1) (32 words)

// ---------------------------------------------------------------------------
// Threefry-2x32, key (0,42), JAX partitionable path (bit-exact, verified)
// ---------------------------------------------------------------------------
__device__ __forceinline__ void threefry2x32(uint32_t k0, uint32_t k1,
                                             uint32_t& x0, uint32_t& x1) {
    uint32_t ks2 = 0x1BD11BDAu ^ k0 ^ k1;
    x0 += k0; x1 += k1;
#define TF_RND(r) { x0 += x1; x1 = __funnelshift_l(x1, x1, (r)); x1 ^= x0; }
    TF_RND(13) TF_RND(15) TF_RND(26) TF_RND(6)
    x0 += k1;  x1 += ks2 + 1u;
    TF_RND(17) TF_RND(29) TF_RND(16) TF_RND(24)
    x0 += ks2; x1 += k0 + 2u;
    TF_RND(13) TF_RND(15) TF_RND(26) TF_RND(6)
    x0 += k0;  x1 += k1 + 3u;
    TF_RND(17) TF_RND(29) TF_RND(16) TF_RND(24)
    x0 += k1;  x1 += ks2 + 4u;
    TF_RND(13) TF_RND(15) TF_RND(26) TF_RND(6)
    x0 += ks2; x1 += k0 + 5u;
#undef TF_RND
}

// ---------------------------------------------------------------------------
// pack helpers
// ---------------------------------------------------------------------------
__device__ __forceinline__ uint32_t pack2(float lo, float hi) {      // bf16x2
    uint32_t r;
    asm("cvt.rn.bf16x2.f32 %0, %1, %2;" : "=r"(r) : "f"(hi), "f"(lo));
    return r;
}
__device__ __forceinline__ float blo(uint32_t w) { return __uint_as_float(w << 16); }
__device__ __forceinline__ float bhi(uint32_t w) { return __uint_as_float(w & 0xffff0000u); }
__device__ __forceinline__ void split2(float a, float b, uint32_t& h, uint32_t& l) {
    h = pack2(a, b);
    l = pack2(a - blo(h), b - bhi(h));
}
__device__ __forceinline__ uint32_t pack2h(float lo, float hi) {     // f16x2
    uint32_t r;
    asm("cvt.rn.f16x2.f32 %0, %1, %2;" : "=r"(r) : "f"(hi), "f"(lo));
    return r;
}
// fp16 hi/lo split (P pack): h = rn(a,b); l = rn(a-h.lo, b-h.hi)
__device__ __forceinline__ void split2h(float a, float b, uint32_t& h, uint32_t& l) {
    uint32_t hh = pack2h(a, b);
    float fa, fb;
    asm("{.reg .b16 x,y;\n mov.b32 {x,y}, %2;\n cvt.f32.f16 %0, x;\n cvt.f32.f16 %1, y;}"
        : "=f"(fa), "=f"(fb) : "r"(hh));
    h = hh;
    l = pack2h(a - fa, b - fb);
}

// ---------------------------------------------------------------------------
// Kernel 1: mask (0..8191) + K convert (8192..9215) + V convert (9216..10239)
// ---------------------------------------------------------------------------
#define MASK_BLKS 8192
#define KC_BLKS   1024
#define VSTR      65

__global__ void __launch_bounds__(256) prep_kernel(const float* __restrict__ K,
                                                   const float* __restrict__ V) {
    __shared__ float vsm[64 * VSTR];
    const int b = blockIdx.x;
    const int tid = threadIdx.x;

    if (b < MASK_BLKS) {
        uint32_t base = (uint32_t)(b * 256 + tid) * 32u;
        uint32_t w = 0u;
#pragma unroll 4
        for (int i = 0; i < 32; i++) {
            uint32_t x0 = 0u, x1 = base + (uint32_t)i;
            threefry2x32(0u, 42u, x0, x1);
            w |= (((x0 ^ x1) < KEEP_THRESH) ? 1u : 0u) << i;
        }
        g_mask[b * 256 + tid] = w;
    } else if (b < MASK_BLKS + KC_BLKS) {
        // ---- K convert: bf16 hi/lo (verified path, unchanged) ----
        int grow = (b - MASK_BLKS) * 64 + (tid >> 2);
        int q = tid & 3;
        const float4* src = reinterpret_cast<const float4*>(K + grow * 64 + q * 16);
        uint32_t hw[8], lw[8];
#pragma unroll
        for (int i = 0; i < 4; i++) {
            float4 v = src[i];
            split2(v.x, v.y, hw[2 * i],     lw[2 * i]);
            split2(v.z, v.w, hw[2 * i + 1], lw[2 * i + 1]);
        }
        uint32_t* dst = g_k + grow * 64;
        *reinterpret_cast<uint4*>(dst + 8 * q)      = make_uint4(hw[0], hw[1], hw[2], hw[3]);
        *reinterpret_cast<uint4*>(dst + 8 * q + 4)  = make_uint4(hw[4], hw[5], hw[6], hw[7]);
        *reinterpret_cast<uint4*>(dst + 32 + 8 * q)     = make_uint4(lw[0], lw[1], lw[2], lw[3]);
        *reinterpret_cast<uint4*>(dst + 32 + 8 * q + 4) = make_uint4(lw[4], lw[5], lw[6], lw[7]);
    } else {
        // ---- V convert: transpose tile, single fp16 ----
        int bb = b - MASK_BLKS - KC_BLKS;               // bh*16 + kt
        const float* Vt = V + (size_t)bb * 64 * 64;
#pragma unroll
        for (int i = 0; i < 4; i++) {
            int lin = tid + (i << 8);
            int row = lin >> 4, qd = (lin & 15) << 2;
            float4 v = *reinterpret_cast<const float4*>(Vt + row * 64 + qd);
            float* d = vsm + row * VSTR + qd;
            d[0] = v.x; d[1] = v.y; d[2] = v.z; d[3] = v.w;
        }
        __syncthreads();
        int od = tid >> 2;                              // d row 0..63
        int kq = tid & 3;                               // kp octet
        uint32_t w[8];
#pragma unroll
        for (int j = 0; j < 8; j++) {
            int kp = kq * 8 + j;
            float f0 = vsm[(2 * kp) * VSTR + od];
            float f1 = vsm[(2 * kp + 1) * VSTR + od];
            w[j] = pack2h(f0, f1);                      // lo=key 2kp, hi=2kp+1
        }
        uint32_t* dst = g_v + ((size_t)bb * 64 + od) * 32 + 8 * kq;
        *reinterpret_cast<uint4*>(dst)     = make_uint4(w[0], w[1], w[2], w[3]);
        *reinterpret_cast<uint4*>(dst + 4) = make_uint4(w[4], w[5], w[6], w[7]);
    }
}

// ---------------------------------------------------------------------------
// Attention: double-buffered cp.async; QK bf16 3-term, PV fp16 2-term
// ---------------------------------------------------------------------------
__device__ __forceinline__ void mma16(float d[4], const uint32_t a[4],
                                      uint32_t b0, uint32_t b1) {
    asm volatile(
        "mma.sync.aligned.m16n8k16.row.col.f32.bf16.bf16.f32 "
        "{%0,%1,%2,%3}, {%4,%5,%6,%7}, {%8,%9}, {%0,%1,%2,%3};"
        : "+f"(d[0]), "+f"(d[1]), "+f"(d[2]), "+f"(d[3])
        : "r"(a[0]), "r"(a[1]), "r"(a[2]), "r"(a[3]), "r"(b0), "r"(b1));
}
__device__ __forceinline__ void mma16h(float d[4], const uint32_t a[4],
                                       uint32_t b0, uint32_t b1) {
    asm volatile(
        "mma.sync.aligned.m16n8k16.row.col.f32.f16.f16.f32 "
        "{%0,%1,%2,%3}, {%4,%5,%6,%7}, {%8,%9}, {%0,%1,%2,%3};"
        : "+f"(d[0]), "+f"(d[1]), "+f"(d[2]), "+f"(d[3])
        : "r"(a[0]), "r"(a[1]), "r"(a[2]), "r"(a[3]), "r"(b0), "r"(b1));
}
__device__ __forceinline__ void ldm_x4(uint32_t r[4], uint32_t addr) {
    asm volatile("ldmatrix.sync.aligned.m8n8.x4.shared.b16 {%0,%1,%2,%3}, [%4];"
                 : "=r"(r[0]), "=r"(r[1]), "=r"(r[2]), "=r"(r[3]) : "r"(addr));
}
__device__ __forceinline__ void cp16(uint32_t saddr, const void* g) {
    asm volatile("cp.async.cg.shared.global [%0], [%1], 16;"
                 :: "r"(saddr), "l"(g));
}

#define PW 36   // bf16x2/f16x2 word stride: 144 B/row, conflict-free ldmatrix

// smem word offsets: Q + two K/V buffers (KH, KL, V per buffer)
#define W_QH  0
#define W_QL  (128 * PW)                 // 4608
#define W_BUF (2 * 128 * PW)             // 9216
#define BUFW  (3 * 64 * PW)              // 6912 words per buffer
#define W_KH0 (W_BUF)
#define W_KL0 (W_BUF + 64 * PW)
#define W_V0  (W_BUF + 2 * 64 * PW)
#define W_TOT (W_BUF + 2 * BUFW)         // 23040 words = 92160 B -> 2 CTAs/SM

__global__ void __launch_bounds__(256, 2)
attn_kernel(const float* __restrict__ Q, const uint32_t* __restrict__ scale_ptr,
            float* __restrict__ O) {
    extern __shared__ uint32_t smw[];

    const int tid  = threadIdx.x;
    const int warp = tid >> 5;
    const int lane = tid & 31;
    const int gid  = lane >> 2;
    const int tig  = lane & 3;
    const int bh   = blockIdx.y;
    const int qb   = blockIdx.x << 7;
    const int r0   = warp * 16 + gid;

    uint32_t sw = *scale_ptr;
    float scale = (sw & 0x7f800000u) ? __uint_as_float(sw) : (float)(int)sw;

    const uint32_t sb = (uint32_t)__cvta_generic_to_shared(smw);
    const uint32_t laneA = (uint32_t)((lane & 15) * PW + ((lane & 16) ? 4 : 0));
    const uint32_t laneBK = (uint32_t)(((lane < 16) ? W_KH0 : W_KL0)
                                       + (lane & 7) * PW + ((lane & 8) ? 4 : 0));
    // V: x4 covers two ks: m0/m1 at col ksp*16 (+0/+4), m2/m3 at +8/+12
    const uint32_t laneBV = (uint32_t)(W_V0 + (lane & 7) * PW
                                       + ((lane & 8) ? 4 : 0) + ((lane & 16) ? 8 : 0));
    const uint32_t aQH = sb + 4u * (W_QH + (uint32_t)(warp * 16) * PW + laneA);
    const uint32_t aQL = sb + 4u * (W_QL + (uint32_t)(warp * 16) * PW + laneA);
    const uint32_t aK0 = sb + 4u * laneBK;
    const uint32_t aV0 = sb + 4u * laneBV;

    // cp.async map: 1536 chunks (K:1024, V:512), 6 per thread
    const uint32_t k_rowbase = (uint32_t)(bh * 1024) * 64u;
    const uint32_t v_rowbase = (uint32_t)(bh * 1024) * 32u;

    // ---- prologue: prefetch tiles 0,1 into buffers 0,1 ----
#pragma unroll
    for (int bf = 0; bf < 2; bf++) {
#pragma unroll
        for (int i = 0; i < 6; i++) {
            int lin = tid + (i << 8);                    // 0..1535
            uint32_t dw;
            const uint32_t* src;
            if (lin < 1024) {
                int r = lin >> 4, c = lin & 15;
                src = g_k + k_rowbase + (uint32_t)((bf * 64 + r) * 64
                        + ((c & 8) ? 32 : 0) + 4 * (c & 7));
                dw = (c < 8 ? W_KH0 : W_KL0) + (uint32_t)(bf * BUFW + r * PW + 4 * (c & 7));
            } else {
                int v = lin - 1024;
                int r = v >> 3, c = v & 7;
                src = g_v + v_rowbase + (uint32_t)((bf * 64 + r) * 32 + 4 * c);
                dw = W_V0 + (uint32_t)(bf * BUFW + r * PW + 4 * c);
            }
            cp16(sb + 4u * dw, src);
        }
        asm volatile("cp.async.commit_group;" ::: "memory");
    }

    // ---- Q prologue: stage scaled hi/lo bf16x2 words into smem ----
    {
        int r = tid >> 1, half = (tid & 1) * 32;
        const float4* Qp = reinterpret_cast<const float4*>(
            Q + ((size_t)bh * S_ + qb + r) * D_ + half);
        int wb = r * PW + (half >> 1);
#pragma unroll
        for (int i = 0; i < 8; i++) {
            float4 v = Qp[i];
            uint32_t h0, l0, h1, l1;
            split2(v.x * scale, v.y * scale, h0, l0);
            split2(v.z * scale, v.w * scale, h1, l1);
            smw[W_QH + wb + 2 * i]     = h0;
            smw[W_QH + wb + 2 * i + 1] = h1;
            smw[W_QL + wb + 2 * i]     = l0;
            smw[W_QL + wb + 2 * i + 1] = l1;
        }
    }

    float m_[2], l_[2];
    float o[8][4];
    m_[0] = m_[1] = -1e30f;
    l_[0] = l_[1] = 0.f;
#pragma unroll
    for (int n = 0; n < 8; n++)
#pragma unroll
        for (int c = 0; c < 4; c++) o[n][c] = 0.f;

#pragma unroll 1
    for (int t = 0; t < 16; t++) {
        // ---- mask prefetch (hidden under QK) ----
        uint2 mw[2];
#pragma unroll
        for (int h = 0; h < 2; h++) {
            size_t rg = (size_t)(bh * S_ + qb + r0 + 8 * h);
            mw[h] = *reinterpret_cast<const uint2*>(g_mask + (rg << 5) + t * 2);
        }

        asm volatile("cp.async.wait_group 1;" ::: "memory");
        __syncthreads();                 // tile t resident for all warps

        const uint32_t boff = (uint32_t)((t & 1) * BUFW) * 4u;
        const uint32_t aK = aK0 + boff;
        const uint32_t aV = aV0 + boff;

        // ---- QK: 3-term bf16 (verified) ----
        float s[8][4];
#pragma unroll
        for (int n = 0; n < 8; n++)
#pragma unroll
            for (int c = 0; c < 4; c++) s[n][c] = 0.f;

#pragma unroll
        for (int ks = 0; ks < 4; ks++) {
            uint32_t qh[4], ql[4];
            ldm_x4(qh, aQH + ks * 32u);
            ldm_x4(ql, aQL + ks * 32u);
#pragma unroll
            for (int n = 0; n < 8; n++) {
                uint32_t kb[4];
                ldm_x4(kb, aK + 4u * (uint32_t)(n * 8 * PW + ks * 8));
                mma16(s[n], qh, kb[0], kb[1]);
                mma16(s[n], ql, kb[0], kb[1]);
                mma16(s[n], qh, kb[2], kb[3]);
            }
        }

        // ---- online softmax ----
#pragma unroll
        for (int h = 0; h < 2; h++) {
            float mx = -1e30f;
#pragma unroll
            for (int n = 0; n < 8; n++)
                mx = fmaxf(mx, fmaxf(s[n][2 * h], s[n][2 * h + 1]));
            mx = fmaxf(mx, __shfl_xor_sync(0xffffffffu, mx, 1));
            mx = fmaxf(mx, __shfl_xor_sync(0xffffffffu, mx, 2));
            float mnew = fmaxf(m_[h], mx);
            float corr = __expf(m_[h] - mnew);
            m_[h] = mnew;
            float sum = 0.f;
#pragma unroll
            for (int n = 0; n < 8; n++) {
                float e0 = __expf(s[n][2 * h] - mnew);
                float e1 = __expf(s[n][2 * h + 1] - mnew);
                s[n][2 * h] = e0;
                s[n][2 * h + 1] = e1;
                sum += e0 + e1;
            }
            sum += __shfl_xor_sync(0xffffffffu, sum, 1);
            sum += __shfl_xor_sync(0xffffffffu, sum, 2);
            l_[h] = l_[h] * corr + sum;
#pragma unroll
            for (int n = 0; n < 8; n++) {
                o[n][2 * h] *= corr;
                o[n][2 * h + 1] *= corr;
            }
        }

        // ---- PV: fp16 2-term (P hi/lo, V single); one x4 feeds two ks ----
#pragma unroll
        for (int ksp = 0; ksp < 2; ksp++) {
            uint32_t aph[2][4], apl[2][4];
#pragma unroll
            for (int kk = 0; kk < 2; kk++) {
                int ks = 2 * ksp + kk;
#pragma unroll
                for (int q = 0; q < 4; q++) {
                    int n = 2 * ks + (q >> 1);
                    int h = q & 1;
                    uint32_t word = (n < 4) ? mw[h].x : mw[h].y;
                    int bit0 = (n & 3) * 8 + 2 * tig;
                    float p0 = ((word >> bit0) & 1u) ? s[n][2 * h] : 0.f;
                    float p1 = ((word >> (bit0 + 1)) & 1u) ? s[n][2 * h + 1] : 0.f;
                    int ar = (q >> 1) * 2 + h;
                    split2h(p0, p1, aph[kk][ar], apl[kk][ar]);
                }
            }
#pragma unroll
            for (int n = 0; n < 8; n++) {
                uint32_t vb[4];
                ldm_x4(vb, aV + 4u * (uint32_t)(n * 8 * PW + ksp * 16));
                mma16h(o[n], aph[0], vb[0], vb[1]);
                mma16h(o[n], apl[0], vb[0], vb[1]);
                mma16h(o[n], aph[1], vb[2], vb[3]);
                mma16h(o[n], apl[1], vb[2], vb[3]);
            }
        }

        __syncthreads();                 // all warps done with buf[t&1]

        // ---- prefetch tile t+2 into buf[t&1] ----
        if (t < 14) {
#pragma unroll
            for (int i = 0; i < 6; i++) {
                int lin = tid + (i << 8);
                uint32_t dw;
                const uint32_t* src;
                if (lin < 1024) {
                    int r = lin >> 4, c = lin & 15;
                    src = g_k + k_rowbase + (uint32_t)(((t + 2) * 64 + r) * 64
                            + ((c & 8) ? 32 : 0) + 4 * (c & 7));
                    dw = (c < 8 ? W_KH0 : W_KL0)
                         + (uint32_t)((t & 1) * BUFW + r * PW + 4 * (c & 7));
                } else {
                    int v = lin - 1024;
                    int r = v >> 3, c = v & 7;
                    src = g_v + v_rowbase + (uint32_t)(((t + 2) * 64 + r) * 32 + 4 * c);
                    dw = W_V0 + (uint32_t)((t & 1) * BUFW + r * PW + 4 * c);
                }
                cp16(sb + 4u * dw, src);
            }
        }
        asm volatile("cp.async.commit_group;" ::: "memory");
    }

    // ---- epilogue: O / (0.9 * l) ----
#pragma unroll
    for (int h = 0; h < 2; h++) {
        float inv = 1.f / (0.9f * l_[h]);
        int row = qb + r0 + h * 8;
        float* Op = O + ((size_t)bh * S_ + row) * D_;
#pragma unroll
        for (int n = 0; n < 8; n++) {
            float2 v;
            v.x = o[n][2 * h] * inv;
            v.y = o[n][2 * h + 1] * inv;
            *reinterpret_cast<float2*>(Op + n * 8 + 2 * tig) = v;
        }
    }
}

// ---------------------------------------------------------------------------
extern "C" void kernel_launch(void* const* d_in, const int* in_sizes, int n_in,
                              void* d_out, int out_size) {
    (void)in_sizes; (void)n_in; (void)out_size;
    const float*    Q  = (const float*)d_in[0];
    const float*    K  = (const float*)d_in[1];
    const float*    V  = (const float*)d_in[2];
    const uint32_t* SC = (const uint32_t*)d_in[3];
    float*          O  = (float*)d_out;

    prep_kernel<<<MASK_BLKS + 2 * KC_BLKS, 256>>>(K, V);

    const int smem = W_TOT * (int)sizeof(uint32_t);   // 92160 B
    cudaFuncSetAttribute(attn_kernel,
                         cudaFuncAttributeMaxDynamicSharedMemorySize, smem);
    dim3 grid(S_ / 128, B_ * H_);
    attn_kernel<<<grid, 256, smem>>>(Q, SC, O);
}